// round 13
// baseline (speedup 1.0000x reference)
#include <cuda_runtime.h>
#include <math.h>

#define BB 4
#define CC 512
#define HW 1024
#define KK 64
#define NP2 8    // d2 partial count (C-split)
#define NP4 16   // agg partial count (n-split)
#define NWT 32   // wsum partial tiles

typedef unsigned long long u64;
typedef unsigned int u32;

// ---------------- scratch ----------------
__device__ float g_w1t[CC*KK];            // inv2, c-major [c][k]
__device__ float g_w2t[CC*KK];            // -2*anchor*inv2, c-major [c][k]
__device__ float g_inv[KK*CC];            // inv, k-major
__device__ float g_ck[KK];                // sum_c anchor^2*inv2
__device__ float g_d2p[NP2][BB*KK*HW];    // d2 partials, k-major
__device__ float g_nump[NP4][BB*KK*CC];   // agg partials
__device__ float g_wsp[BB*NWT*KK];        // wsum partials

// ---------------- f32x2 helpers ----------------
__device__ __forceinline__ u64 dup2(float a) {
    u64 r; asm("mov.b64 %0, {%1, %1};" : "=l"(r) : "f"(a)); return r;
}
__device__ __forceinline__ void fma2(u64& d, u64 a, u64 b) {
    asm("fma.rn.f32x2 %0, %1, %2, %0;" : "+l"(d) : "l"(a), "l"(b));
}
__device__ __forceinline__ u64 mul2(u64 a, u64 b) {
    u64 r; asm("mul.rn.f32x2 %0, %1, %2;" : "=l"(r) : "l"(a), "l"(b)); return r;
}
__device__ __forceinline__ float2 unpk(u64 a) {
    float x, y; asm("mov.b64 {%0, %1}, %2;" : "=f"(x), "=f"(y) : "l"(a));
    return make_float2(x, y);
}

// ---------------- cp.async helpers ----------------
__device__ __forceinline__ void cpa16(void* s, const void* g) {
    u32 sa = (u32)__cvta_generic_to_shared(s);
    asm volatile("cp.async.cg.shared.global [%0], [%1], 16;" :: "r"(sa), "l"(g));
}
__device__ __forceinline__ void cpcommit() {
    asm volatile("cp.async.commit_group;" ::: "memory");
}
template<int N> __device__ __forceinline__ void cpwait() {
    asm volatile("cp.async.wait_group %0;" :: "n"(N) : "memory");
}

// ---------------- K1: weights prep ----------------
__global__ void k1_prep(const float* __restrict__ anchor,
                        const float* __restrict__ sigma) {
    int k = blockIdx.x;
    int tid = threadIdx.x;
    __shared__ float red[256];
    float ck = 0.f;
    for (int c = tid; c < CC; c += 256) {
        int idx = k*CC + c;
        float s  = 1.f / (1.f + expf(-sigma[idx]));
        float iv = 1.f / (s + 1e-7f);
        float i2 = iv * iv;
        float a  = anchor[idx];
        g_w1t[c*KK + k] = i2;
        g_w2t[c*KK + k] = -2.f * a * i2;
        g_inv[idx] = iv;
        ck += a * a * i2;
    }
    red[tid] = ck; __syncthreads();
    for (int s = 128; s > 0; s >>= 1) {
        if (tid < s) red[tid] += red[tid + s];
        __syncthreads();
    }
    if (tid == 0) g_ck[k] = red[0];
}

// ---------------- K2: distance GEMM, cp.async double-buffer (R8, unchanged) ----------------
#define S2STRIDE 4288   // 16*132 (x) + 16*68 (w1) + 16*68 (w2)
__global__ void __launch_bounds__(256, 2) k2_dist(const float* __restrict__ x) {
    __shared__ float sm2[2][S2STRIDE];
    int bid = blockIdx.x;
    int cs = bid & 7;
    int nt = (bid >> 3) & 7;
    int b  = bid >> 6;
    int c0 = cs * 64, n0 = nt * 128;

    int tid = threadIdx.x;
    int kr = tid >> 5;
    int nr = tid & 31;
    int k0 = kr * 8;

    u64 acc[4][4];
#pragma unroll
    for (int i = 0; i < 4; i++)
#pragma unroll
        for (int j = 0; j < 4; j++) acc[i][j] = 0ull;

    auto fill = [&](int s, int cc) {
        float* xs = sm2[s];
        float* w1 = xs + 16*132;
        float* w2 = w1 + 16*68;
#pragma unroll
        for (int l = 0; l < 2; l++) {
            int slot = tid + l * 256;
            int row = slot >> 5;
            int col = (slot & 31) << 2;
            cpa16(&xs[row*132 + col], &x[(b*CC + c0 + cc + row)*HW + n0 + col]);
        }
        {
            int rc = tid >> 4;
            int kk = (tid & 15) << 2;
            cpa16(&w1[rc*68 + kk], &g_w1t[(c0 + cc + rc)*KK + kk]);
            cpa16(&w2[rc*68 + kk], &g_w2t[(c0 + cc + rc)*KK + kk]);
        }
        cpcommit();
    };

    auto comp = [&](int s) {
        float* xs = sm2[s];
        float* w1 = xs + 16*132;
        float* w2 = w1 + 16*68;
#pragma unroll
        for (int c = 0; c < 16; c++) {
            float4 xa = *(const float4*)&xs[c*132 + nr*4];
            ulonglong2 w1a = *(const ulonglong2*)&w1[c*68 + k0];
            ulonglong2 w1b = *(const ulonglong2*)&w1[c*68 + k0 + 4];
            ulonglong2 w2a = *(const ulonglong2*)&w2[c*68 + k0];
            ulonglong2 w2b = *(const ulonglong2*)&w2[c*68 + k0 + 4];
            u64 w1p[4] = {w1a.x, w1a.y, w1b.x, w1b.y};
            u64 w2p[4] = {w2a.x, w2a.y, w2b.x, w2b.y};
            float xn[4] = {xa.x, xa.y, xa.z, xa.w};
#pragma unroll
            for (int j = 0; j < 4; j++) {
                u64 xd = dup2(xn[j]);
                u64 xq = mul2(xd, xd);
#pragma unroll
                for (int kp = 0; kp < 4; kp++) {
                    fma2(acc[kp][j], xq, w1p[kp]);
                    fma2(acc[kp][j], xd, w2p[kp]);
                }
            }
        }
    };

    fill(0, 0);
    fill(1, 16); cpwait<1>(); __syncthreads(); comp(0); __syncthreads();
    fill(0, 32); cpwait<1>(); __syncthreads(); comp(1); __syncthreads();
    fill(1, 48); cpwait<1>(); __syncthreads(); comp(0); __syncthreads();
                 cpwait<0>(); __syncthreads(); comp(1);

#pragma unroll
    for (int kp = 0; kp < 4; kp++) {
        float2 p0 = unpk(acc[kp][0]), p1 = unpk(acc[kp][1]);
        float2 p2 = unpk(acc[kp][2]), p3 = unpk(acc[kp][3]);
        int klo = k0 + 2*kp;
        int base = (b*KK + klo)*HW + n0 + nr*4;
        *(float4*)&g_d2p[cs][base]      = make_float4(p0.x, p1.x, p2.x, p3.x);
        *(float4*)&g_d2p[cs][base + HW] = make_float4(p0.y, p1.y, p2.y, p3.y);
    }
}

// ---------------- K23: partial reduce + softmax + wsum partials (unchanged) ----------------
__global__ void __launch_bounds__(512, 2) k23(float* __restrict__ soft_out) {
    int b    = blockIdx.x >> 5;
    int tile = blockIdx.x & 31;
    int n0   = tile * 32;
    int tid  = threadIdx.x;
    __shared__ float sm[64][36];

    {
        int k  = tid >> 3;
        int n4 = (tid & 7) << 2;
        int base = (b*KK + k)*HW + n0 + n4;
        float4 s = make_float4(0.f, 0.f, 0.f, 0.f);
#pragma unroll
        for (int p = 0; p < NP2; p++) {
            float4 v = *(const float4*)&g_d2p[p][base];
            s.x += v.x; s.y += v.y; s.z += v.z; s.w += v.w;
        }
        float ck = g_ck[k];
        s.x = -0.5f*(s.x + ck); s.y = -0.5f*(s.y + ck);
        s.z = -0.5f*(s.z + ck); s.w = -0.5f*(s.w + ck);
        *(float4*)&sm[k][n4] = s;
    }
    __syncthreads();

    {
        int n   = tid >> 4;
        int sub = tid & 15;
        float v[4];
        float mx = -3.4e38f;
#pragma unroll
        for (int i = 0; i < 4; i++) {
            v[i] = sm[sub + 16*i][n];
            mx = fmaxf(mx, v[i]);
        }
#pragma unroll
        for (int m = 1; m < 16; m <<= 1)
            mx = fmaxf(mx, __shfl_xor_sync(0xffffffffu, mx, m));
        float s = 0.f;
#pragma unroll
        for (int i = 0; i < 4; i++) { v[i] = __expf(v[i] - mx); s += v[i]; }
#pragma unroll
        for (int m = 1; m < 16; m <<= 1)
            s += __shfl_xor_sync(0xffffffffu, s, m);
        float is = 1.f / s;
#pragma unroll
        for (int i = 0; i < 4; i++)
            sm[sub + 16*i][n] = v[i] * is;
    }
    __syncthreads();

    {
        int k  = tid >> 3;
        int n4 = (tid & 7) << 2;
        *(float4*)&soft_out[(b*KK + k)*HW + n0 + n4] = *(const float4*)&sm[k][n4];
    }
    {
        int k   = tid >> 3;
        int sub = tid & 7;
        float w = 0.f;
#pragma unroll
        for (int j = 0; j < 4; j++) w += sm[k][sub*4 + j];
#pragma unroll
        for (int m = 1; m < 8; m <<= 1)
            w += __shfl_xor_sync(0xffffffffu, w, m);
        if (sub == 0) g_wsp[(b*NWT + tile)*KK + k] = w;
    }
}

// ---------------- K4 v5: SIMT f32x2, inner-dim (n) vectorized dot products ----------------
// grid 256 = 4b x 4ct x 16ns, 256 thr. Block: 64k x 128c x 64n (4 stages of 16n).
// Thread: 8k (warp-uniform k0) x 4c (c = cb + cr + 32j). acc2[k][j] accumulates
// n-pairs; one horizontal add at the end. Both operands consumed in natural
// n-contiguous layout -> cp.async fills, no transposes, full fp32 precision.
// s loads: warp-uniform broadcast LDS.128. x loads: lanes on consecutive rows,
// pitch 20 words -> 2-way max conflict. Per 4n sub-iter: 12 LDS.128 + 64 FMA2.
#define K4P 20
__global__ void __launch_bounds__(256, 2) k4_agg(const float* __restrict__ x,
                                                 const float* __restrict__ soft) {
    __shared__ float xs[2][128*K4P];
    __shared__ float ss[2][64*K4P];
    int bid = blockIdx.x;
    int ns = bid & 15;
    int ct = (bid >> 4) & 3;
    int b  = bid >> 6;
    int n0 = ns * 64;
    int cb = ct * 128;

    int tid = threadIdx.x;
    int kr  = tid >> 5;          // warp-uniform
    int cr  = tid & 31;
    int k0  = kr * 8;

    u64 acc[8][4];
#pragma unroll
    for (int k = 0; k < 8; k++)
#pragma unroll
        for (int j = 0; j < 4; j++) acc[k][j] = 0ull;

    auto fill = [&](int s, int st) {
        // x: 128 rows x 16 floats = 512 f4 slots (2 per thread)
#pragma unroll
        for (int l = 0; l < 2; l++) {
            int slot = tid + l * 256;
            int c  = slot >> 2;
            int f4 = slot & 3;
            cpa16(&xs[s][c*K4P + f4*4],
                  &x[(b*CC + cb + c)*HW + n0 + st*16 + f4*4]);
        }
        // soft: 64 rows x 16 floats = 256 f4 slots (1 per thread)
        {
            int k  = tid >> 2;
            int f4 = tid & 3;
            cpa16(&ss[s][k*K4P + f4*4],
                  &soft[(b*KK + k)*HW + n0 + st*16 + f4*4]);
        }
        cpcommit();
    };

    auto comp = [&](int s) {
#pragma unroll
        for (int sub = 0; sub < 4; sub++) {
            u64 s2[8][2];
#pragma unroll
            for (int k = 0; k < 8; k++) {
                ulonglong2 v = *(const ulonglong2*)&ss[s][(k0 + k)*K4P + sub*4];
                s2[k][0] = v.x; s2[k][1] = v.y;
            }
#pragma unroll
            for (int j = 0; j < 4; j++) {
                ulonglong2 xv = *(const ulonglong2*)&xs[s][(cr + 32*j)*K4P + sub*4];
#pragma unroll
                for (int k = 0; k < 8; k++) {
                    fma2(acc[k][j], s2[k][0], xv.x);
                    fma2(acc[k][j], s2[k][1], xv.y);
                }
            }
        }
    };

    fill(0, 0);
    fill(1, 1); cpwait<1>(); __syncthreads(); comp(0); __syncthreads();
    fill(0, 2); cpwait<1>(); __syncthreads(); comp(1); __syncthreads();
    fill(1, 3); cpwait<1>(); __syncthreads(); comp(0); __syncthreads();
                cpwait<0>(); __syncthreads(); comp(1);

    // horizontal add + coalesced scalar stores (lanes = consecutive c)
#pragma unroll
    for (int k = 0; k < 8; k++)
#pragma unroll
        for (int j = 0; j < 4; j++) {
            float2 p = unpk(acc[k][j]);
            g_nump[ns][(b*KK + k0 + k)*CC + cb + cr + 32*j] = p.x + p.y;
        }
}

// ---------------- K5: epilogue + row normalize + folded flat normalize ----------------
__global__ void k5_epilogue(const float* __restrict__ anchor,
                            float* __restrict__ out) {
    int bk = blockIdx.x;
    int k  = bk & 63;
    int b  = bk >> 6;
    int tid = threadIdx.x;
    __shared__ float red[256];

    float ws = 0.f;
#pragma unroll
    for (int p = 0; p < NWT; p++) ws += g_wsp[(b*NWT + p)*KK + k];

    float invden = 1.f / (ws + 1e-7f);
    float node[2];
    float sq = 0.f;
#pragma unroll
    for (int l = 0; l < 2; l++) {
        int c = tid + l * 256;
        int gi = bk * CC + c;
        float num = 0.f;
#pragma unroll
        for (int p = 0; p < NP4; p++) num += g_nump[p][gi];
        num = (num - ws * anchor[k*CC + c]) * g_inv[k*CC + c];
        float nd = num * invden;
        node[l] = nd;
        sq += nd * nd;
    }
    red[tid] = sq; __syncthreads();
    for (int s = 128; s > 0; s >>= 1) {
        if (tid < s) red[tid] += red[tid + s];
        __syncthreads();
    }
    float total = red[0];
    float scale = 0.125f / fmaxf(sqrtf(total), 1e-12f);
#pragma unroll
    for (int l = 0; l < 2; l++)
        out[bk * CC + tid + l * 256] = node[l] * scale;
}

// ---------------- launch ----------------
extern "C" void kernel_launch(void* const* d_in, const int* in_sizes, int n_in,
                              void* d_out, int out_size) {
    const float* x      = (const float*)d_in[0];
    const float* anchor = (const float*)d_in[1];
    const float* sigma  = (const float*)d_in[2];
    float* out = (float*)d_out;
    float* nodes_out = out;                 // B*K*C floats
    float* soft_out  = out + BB*KK*CC;      // B*K*HW floats

    k1_prep    <<<KK, 256>>>(anchor, sigma);
    k2_dist    <<<256, 256>>>(x);
    k23        <<<128, 512>>>(soft_out);
    k4_agg     <<<256, 256>>>(x, soft_out);
    k5_epilogue<<<BB*KK, 256>>>(anchor, nodes_out);
}

// round 14
// speedup vs baseline: 1.0035x; 1.0035x over previous
#include <cuda_runtime.h>
#include <math.h>

#define BB 4
#define CC 512
#define HW 1024
#define KK 64
#define NP2 8    // d2 partial count (C-split)
#define NP4 16   // agg partial count (n-split)
#define NWT 32   // wsum partial tiles

typedef unsigned long long u64;
typedef unsigned int u32;

// ---------------- scratch ----------------
__device__ float g_w1t[CC*KK];            // inv2, c-major [c][k]
__device__ float g_w2t[CC*KK];            // -2*anchor*inv2, c-major [c][k]
__device__ float g_inv[KK*CC];            // inv, k-major
__device__ float g_ck[KK];                // sum_c anchor^2*inv2
__device__ float g_d2p[NP2][BB*KK*HW];    // d2 partials, k-major
__device__ float g_nump[NP4][BB*KK*CC];   // agg partials
__device__ float g_wsp[BB*NWT*KK];        // wsum partials
__device__ float g_xt[BB*HW*CC];          // x transposed [b][n][c] (from k2)
__device__ float g_st[BB*HW*KK];          // soft transposed [b][n][k] (from k23)

// ---------------- f32x2 helpers ----------------
__device__ __forceinline__ u64 dup2(float a) {
    u64 r; asm("mov.b64 %0, {%1, %1};" : "=l"(r) : "f"(a)); return r;
}
__device__ __forceinline__ void fma2(u64& d, u64 a, u64 b) {
    asm("fma.rn.f32x2 %0, %1, %2, %0;" : "+l"(d) : "l"(a), "l"(b));
}
__device__ __forceinline__ u64 mul2(u64 a, u64 b) {
    u64 r; asm("mul.rn.f32x2 %0, %1, %2;" : "=l"(r) : "l"(a), "l"(b)); return r;
}
__device__ __forceinline__ float2 unpk(u64 a) {
    float x, y; asm("mov.b64 {%0, %1}, %2;" : "=f"(x), "=f"(y) : "l"(a));
    return make_float2(x, y);
}

// ---------------- cp.async helpers ----------------
__device__ __forceinline__ void cpa16(void* s, const void* g) {
    u32 sa = (u32)__cvta_generic_to_shared(s);
    asm volatile("cp.async.cg.shared.global [%0], [%1], 16;" :: "r"(sa), "l"(g));
}
__device__ __forceinline__ void cpcommit() {
    asm volatile("cp.async.commit_group;" ::: "memory");
}
template<int N> __device__ __forceinline__ void cpwait() {
    asm volatile("cp.async.wait_group %0;" :: "n"(N) : "memory");
}

// ---------------- K1: weights prep ----------------
__global__ void k1_prep(const float* __restrict__ anchor,
                        const float* __restrict__ sigma) {
    int k = blockIdx.x;
    int tid = threadIdx.x;
    __shared__ float red[256];
    float ck = 0.f;
    for (int c = tid; c < CC; c += 256) {
        int idx = k*CC + c;
        float s  = 1.f / (1.f + expf(-sigma[idx]));
        float iv = 1.f / (s + 1e-7f);
        float i2 = iv * iv;
        float a  = anchor[idx];
        g_w1t[c*KK + k] = i2;
        g_w2t[c*KK + k] = -2.f * a * i2;
        g_inv[idx] = iv;
        ck += a * a * i2;
    }
    red[tid] = ck; __syncthreads();
    for (int s = 128; s > 0; s >>= 1) {
        if (tid < s) red[tid] += red[tid + s];
        __syncthreads();
    }
    if (tid == 0) g_ck[k] = red[0];
}

// ---------------- K2: distance GEMM + xT side-product ----------------
// R8 structure; after each comp the 16c x 128n chunk is transposed out to g_xt.
#define S2STRIDE 4288   // 16*132 (x) + 16*68 (w1) + 16*68 (w2)
__global__ void __launch_bounds__(256, 2) k2_dist(const float* __restrict__ x) {
    __shared__ float sm2[2][S2STRIDE];
    int bid = blockIdx.x;
    int cs = bid & 7;
    int nt = (bid >> 3) & 7;
    int b  = bid >> 6;
    int c0 = cs * 64, n0 = nt * 128;

    int tid = threadIdx.x;
    int kr = tid >> 5;
    int nr = tid & 31;
    int k0 = kr * 8;

    u64 acc[4][4];
#pragma unroll
    for (int i = 0; i < 4; i++)
#pragma unroll
        for (int j = 0; j < 4; j++) acc[i][j] = 0ull;

    auto fill = [&](int s, int cc) {
        float* xs = sm2[s];
        float* w1 = xs + 16*132;
        float* w2 = w1 + 16*68;
#pragma unroll
        for (int l = 0; l < 2; l++) {
            int slot = tid + l * 256;
            int row = slot >> 5;
            int col = (slot & 31) << 2;
            cpa16(&xs[row*132 + col], &x[(b*CC + c0 + cc + row)*HW + n0 + col]);
        }
        {
            int rc = tid >> 4;
            int kk = (tid & 15) << 2;
            cpa16(&w1[rc*68 + kk], &g_w1t[(c0 + cc + rc)*KK + kk]);
            cpa16(&w2[rc*68 + kk], &g_w2t[(c0 + cc + rc)*KK + kk]);
        }
        cpcommit();
    };

    auto comp = [&](int s) {
        float* xs = sm2[s];
        float* w1 = xs + 16*132;
        float* w2 = w1 + 16*68;
#pragma unroll
        for (int c = 0; c < 16; c++) {
            float4 xa = *(const float4*)&xs[c*132 + nr*4];
            ulonglong2 w1a = *(const ulonglong2*)&w1[c*68 + k0];
            ulonglong2 w1b = *(const ulonglong2*)&w1[c*68 + k0 + 4];
            ulonglong2 w2a = *(const ulonglong2*)&w2[c*68 + k0];
            ulonglong2 w2b = *(const ulonglong2*)&w2[c*68 + k0 + 4];
            u64 w1p[4] = {w1a.x, w1a.y, w1b.x, w1b.y};
            u64 w2p[4] = {w2a.x, w2a.y, w2b.x, w2b.y};
            float xn[4] = {xa.x, xa.y, xa.z, xa.w};
#pragma unroll
            for (int j = 0; j < 4; j++) {
                u64 xd = dup2(xn[j]);
                u64 xq = mul2(xd, xd);
#pragma unroll
                for (int kp = 0; kp < 4; kp++) {
                    fma2(acc[kp][j], xq, w1p[kp]);
                    fma2(acc[kp][j], xd, w2p[kp]);
                }
            }
        }
    };

    // transpose chunk (16c x 128n) from stage s to g_xt[b][n][c0+cc+c]
    int tw = tid >> 5, tl = tid & 31;
    int tc = tl & 15;
    int tnh = tl >> 4;
    auto twrite = [&](int s, int cc) {
        float* xs = sm2[s];
#pragma unroll
        for (int it = 0; it < 8; it++) {
            int n = it*16 + tw*2 + tnh;
            g_xt[(b*HW + n0 + n)*CC + c0 + cc + tc] = xs[tc*132 + n];
        }
    };

    fill(0, 0);
    fill(1, 16); cpwait<1>(); __syncthreads(); comp(0); twrite(0, 0);  __syncthreads();
    fill(0, 32); cpwait<1>(); __syncthreads(); comp(1); twrite(1, 16); __syncthreads();
    fill(1, 48); cpwait<1>(); __syncthreads(); comp(0); twrite(0, 32); __syncthreads();
                 cpwait<0>(); __syncthreads(); comp(1); twrite(1, 48);

#pragma unroll
    for (int kp = 0; kp < 4; kp++) {
        float2 p0 = unpk(acc[kp][0]), p1 = unpk(acc[kp][1]);
        float2 p2 = unpk(acc[kp][2]), p3 = unpk(acc[kp][3]);
        int klo = k0 + 2*kp;
        int base = (b*KK + klo)*HW + n0 + nr*4;
        *(float4*)&g_d2p[cs][base]      = make_float4(p0.x, p1.x, p2.x, p3.x);
        *(float4*)&g_d2p[cs][base + HW] = make_float4(p0.y, p1.y, p2.y, p3.y);
    }
}

// ---------------- K23: reduce + softmax + wsum + softT side-product ----------------
__global__ void __launch_bounds__(512, 2) k23(float* __restrict__ soft_out) {
    int b    = blockIdx.x >> 5;
    int tile = blockIdx.x & 31;
    int n0   = tile * 32;
    int tid  = threadIdx.x;
    __shared__ float sm[64][36];

    {
        int k  = tid >> 3;
        int n4 = (tid & 7) << 2;
        int base = (b*KK + k)*HW + n0 + n4;
        float4 s = make_float4(0.f, 0.f, 0.f, 0.f);
#pragma unroll
        for (int p = 0; p < NP2; p++) {
            float4 v = *(const float4*)&g_d2p[p][base];
            s.x += v.x; s.y += v.y; s.z += v.z; s.w += v.w;
        }
        float ck = g_ck[k];
        s.x = -0.5f*(s.x + ck); s.y = -0.5f*(s.y + ck);
        s.z = -0.5f*(s.z + ck); s.w = -0.5f*(s.w + ck);
        *(float4*)&sm[k][n4] = s;
    }
    __syncthreads();

    {
        int n   = tid >> 4;
        int sub = tid & 15;
        float v[4];
        float mx = -3.4e38f;
#pragma unroll
        for (int i = 0; i < 4; i++) {
            v[i] = sm[sub + 16*i][n];
            mx = fmaxf(mx, v[i]);
        }
#pragma unroll
        for (int m = 1; m < 16; m <<= 1)
            mx = fmaxf(mx, __shfl_xor_sync(0xffffffffu, mx, m));
        float s = 0.f;
#pragma unroll
        for (int i = 0; i < 4; i++) { v[i] = __expf(v[i] - mx); s += v[i]; }
#pragma unroll
        for (int m = 1; m < 16; m <<= 1)
            s += __shfl_xor_sync(0xffffffffu, s, m);
        float is = 1.f / s;
#pragma unroll
        for (int i = 0; i < 4; i++)
            sm[sub + 16*i][n] = v[i] * is;
    }
    __syncthreads();

    {   // k-major output
        int k  = tid >> 3;
        int n4 = (tid & 7) << 2;
        *(float4*)&soft_out[(b*KK + k)*HW + n0 + n4] = *(const float4*)&sm[k][n4];
    }
    {   // n-major softT for k4
        int n  = tid >> 4;      // 0..31
        int kq = tid & 15;      // 4 k each
        float4 v = make_float4(sm[kq*4 + 0][n], sm[kq*4 + 1][n],
                               sm[kq*4 + 2][n], sm[kq*4 + 3][n]);
        *(float4*)&g_st[(b*HW + n0 + n)*KK + kq*4] = v;
    }
    {   // wsum partials
        int k   = tid >> 3;
        int sub = tid & 7;
        float w = 0.f;
#pragma unroll
        for (int j = 0; j < 4; j++) w += sm[k][sub*4 + j];
#pragma unroll
        for (int m = 1; m < 8; m <<= 1)
            w += __shfl_xor_sync(0xffffffffu, w, m);
        if (sub == 0) g_wsp[(b*NWT + tile)*KK + k] = w;
    }
}

// ---------------- K4 v6: k2-clone on transposed operands ----------------
// grid 256 = 4b x 4ct x 16ns, 256 thr. Block: 64k x 128c x 64n (4 chunks of 16n).
// Operands inner(n)-major: xT[n][c] (g_xt), softT[n][k] (g_st). Thread 8k x 4c.
// Per n-iter: 1 LDS.128 (x) + 2 broadcast LDS.128 (softT pairs) + 4 dup2 +
// 16 fma2 for 64 MAC -- k2's exact instruction mix, full fp32.
#define S4STRIDE 3200   // 16*132 (xT) + 16*68 (softT)
__global__ void __launch_bounds__(256, 2) k4_agg() {
    __shared__ float sm4[2][S4STRIDE];
    int bid = blockIdx.x;
    int ns = bid & 15;
    int ct = (bid >> 4) & 3;
    int b  = bid >> 6;
    int n0 = ns * 64;
    int cb = ct * 128;

    int tid = threadIdx.x;
    int kr = tid >> 5;     // warp-uniform -> k0 = kr*8
    int cr = tid & 31;     // c = cb + cr*4 + {0..3}
    int k0 = kr * 8;

    u64 acc[4][4];         // [k-pair][c]
#pragma unroll
    for (int i = 0; i < 4; i++)
#pragma unroll
        for (int j = 0; j < 4; j++) acc[i][j] = 0ull;

    auto fill = [&](int s, int nc) {
        float* xts = sm4[s];
        float* sts = xts + 16*132;
#pragma unroll
        for (int l = 0; l < 2; l++) {
            int slot = tid + l * 256;            // 512 f4: 16n x 32 c-f4
            int row = slot >> 5;
            int col = (slot & 31) << 2;
            cpa16(&xts[row*132 + col], &g_xt[(b*HW + n0 + nc + row)*CC + cb + col]);
        }
        {
            int row = tid >> 4;                  // 256 f4: 16n x 16 k-f4
            int col = (tid & 15) << 2;
            cpa16(&sts[row*68 + col], &g_st[(b*HW + n0 + nc + row)*KK + col]);
        }
        cpcommit();
    };

    auto comp = [&](int s) {
        float* xts = sm4[s];
        float* sts = xts + 16*132;
#pragma unroll
        for (int n = 0; n < 16; n++) {
            float4 xa = *(const float4*)&xts[n*132 + cr*4];
            ulonglong2 sa = *(const ulonglong2*)&sts[n*68 + k0];      // broadcast
            ulonglong2 sb = *(const ulonglong2*)&sts[n*68 + k0 + 4];  // broadcast
            u64 sp[4] = {sa.x, sa.y, sb.x, sb.y};
            float xn[4] = {xa.x, xa.y, xa.z, xa.w};
#pragma unroll
            for (int j = 0; j < 4; j++) {
                u64 xd = dup2(xn[j]);
#pragma unroll
                for (int kp = 0; kp < 4; kp++)
                    fma2(acc[kp][j], xd, sp[kp]);
            }
        }
    };

    fill(0, 0);
    fill(1, 16); cpwait<1>(); __syncthreads(); comp(0); __syncthreads();
    fill(0, 32); cpwait<1>(); __syncthreads(); comp(1); __syncthreads();
    fill(1, 48); cpwait<1>(); __syncthreads(); comp(0); __syncthreads();
                 cpwait<0>(); __syncthreads(); comp(1);

    // stores: k-pairs -> k-major coalesced float4s
#pragma unroll
    for (int kp = 0; kp < 4; kp++) {
        float2 p0 = unpk(acc[kp][0]), p1 = unpk(acc[kp][1]);
        float2 p2 = unpk(acc[kp][2]), p3 = unpk(acc[kp][3]);
        int klo = k0 + 2*kp;
        int base = (b*KK + klo)*CC + cb + cr*4;
        *(float4*)&g_nump[ns][base]      = make_float4(p0.x, p1.x, p2.x, p3.x);
        *(float4*)&g_nump[ns][base + CC] = make_float4(p0.y, p1.y, p2.y, p3.y);
    }
}

// ---------------- K5: epilogue + row normalize + folded flat normalize ----------------
__global__ void k5_epilogue(const float* __restrict__ anchor,
                            float* __restrict__ out) {
    int bk = blockIdx.x;
    int k  = bk & 63;
    int b  = bk >> 6;
    int tid = threadIdx.x;
    __shared__ float red[256];

    float ws = 0.f;
#pragma unroll
    for (int p = 0; p < NWT; p++) ws += g_wsp[(b*NWT + p)*KK + k];

    float invden = 1.f / (ws + 1e-7f);
    float node[2];
    float sq = 0.f;
#pragma unroll
    for (int l = 0; l < 2; l++) {
        int c = tid + l * 256;
        int gi = bk * CC + c;
        float num = 0.f;
#pragma unroll
        for (int p = 0; p < NP4; p++) num += g_nump[p][gi];
        num = (num - ws * anchor[k*CC + c]) * g_inv[k*CC + c];
        float nd = num * invden;
        node[l] = nd;
        sq += nd * nd;
    }
    red[tid] = sq; __syncthreads();
    for (int s = 128; s > 0; s >>= 1) {
        if (tid < s) red[tid] += red[tid + s];
        __syncthreads();
    }
    float total = red[0];
    float scale = 0.125f / fmaxf(sqrtf(total), 1e-12f);
#pragma unroll
    for (int l = 0; l < 2; l++)
        out[bk * CC + tid + l * 256] = node[l] * scale;
}

// ---------------- launch ----------------
extern "C" void kernel_launch(void* const* d_in, const int* in_sizes, int n_in,
                              void* d_out, int out_size) {
    const float* x      = (const float*)d_in[0];
    const float* anchor = (const float*)d_in[1];
    const float* sigma  = (const float*)d_in[2];
    float* out = (float*)d_out;
    float* nodes_out = out;                 // B*K*C floats
    float* soft_out  = out + BB*KK*CC;      // B*K*HW floats

    k1_prep    <<<KK, 256>>>(anchor, sigma);
    k2_dist    <<<256, 256>>>(x);
    k23        <<<128, 512>>>(soft_out);
    k4_agg     <<<256, 256>>>();
    k5_epilogue<<<BB*KK, 256>>>(anchor, nodes_out);
}